// round 2
// baseline (speedup 1.0000x reference)
#include <cuda_runtime.h>

#define ULL unsigned long long

// ---- scratch (device globals; cudaMalloc is forbidden) ----
__device__ float g_pre[4u * 256u * 64u * 512u];   // [gate][t][b][h]  134MB
__device__ float g_h[2][64 * 512];                // h double buffer
__device__ unsigned g_bar;                        // grid barrier counter

// ---- f32x2 helpers (sm_103a packed fp32: 2x FFMA throughput) ----
__device__ __forceinline__ ULL pack2(float lo, float hi) {
    ULL d; asm("mov.b64 %0, {%1,%2};" : "=l"(d) : "f"(lo), "f"(hi)); return d;
}
__device__ __forceinline__ void unpack2(ULL v, float& lo, float& hi) {
    asm("mov.b64 {%0,%1}, %2;" : "=f"(lo), "=f"(hi) : "l"(v));
}
__device__ __forceinline__ ULL fma2(ULL a, ULL b, ULL c) {
    ULL d; asm("fma.rn.f32x2 %0, %1, %2, %3;" : "=l"(d) : "l"(a), "l"(b), "l"(c)); return d;
}

// ============================================================================
// Phase 1: gathered SGEMM  C[16384, 2048] = A[16384,4096] x Wcat[4096,2048]
//   A[r, p*256+i] = (x==0 ? 0 : emb[x[b,p,t], i]),  r = t*64 + b
//   column c -> gate = c/512, h = c%512 ; block tile 128x128, BK=16, 8x8/thread
// ============================================================================
__global__ __launch_bounds__(256, 2) void gemm_x_kernel(
    const int* __restrict__ x, const float* __restrict__ emb,
    const float* __restrict__ W0, const float* __restrict__ W1,
    const float* __restrict__ W2, const float* __restrict__ W3,
    const float* __restrict__ b0, const float* __restrict__ b1,
    const float* __restrict__ b2, const float* __restrict__ b3)
{
    __shared__ float As[16][132];   // [k][row], padded (132*4B keeps 16B align)
    __shared__ float Bs[16][128];   // [k][col]
    __shared__ int   sidx[128];

    const int tid = threadIdx.x;
    const int tx = tid & 15, ty = tid >> 4;
    const int bx = blockIdx.x;            // 0..15 : gate / h tile
    const int by = blockIdx.y;            // 0..127 : row tile
    const int gate  = bx >> 2;
    const int hbase = (bx & 3) * 128;
    const float* W    = (gate == 0) ? W0 : (gate == 1) ? W1 : (gate == 2) ? W2 : W3;
    const float* bias = (gate == 0) ? b0 : (gate == 1) ? b1 : (gate == 2) ? b2 : b3;
    const int row0 = by * 128;

    ULL acc[8][4];
    #pragma unroll
    for (int i = 0; i < 8; i++)
        #pragma unroll
        for (int j = 0; j < 4; j++) acc[i][j] = 0ull;

    // loader roles
    const int a_row  = tid >> 1;          // 0..127
    const int a_half = tid & 1;           // which 8 of the 16 k-cols
    const int b_k    = tid >> 4;          // 0..15
    const int b_c    = (tid & 15) * 8;    // 0..120

    float bb[8];
    #pragma unroll
    for (int c = 0; c < 8; c++) bb[c] = bias[hbase + tx * 8 + c];

    for (int p = 0; p < 16; p++) {
        __syncthreads();                  // prev compute done before sidx rewrite
        if (tid < 128) {
            int r = row0 + tid;
            int t = r >> 6, b = r & 63;
            sidx[tid] = x[(b * 16 + p) * 256 + t];
        }
        for (int kt = 0; kt < 16; kt++) {
            __syncthreads();              // tiles free to overwrite (also sidx ready)
            // ---- load A tile (gathered from emb; padding row 0 -> zeros) ----
            {
                int idx = sidx[a_row];
                float4 v0, v1;
                if (idx != 0) {
                    const float4* src = (const float4*)(emb + (size_t)idx * 256 + kt * 16 + a_half * 8);
                    v0 = src[0]; v1 = src[1];
                } else {
                    v0 = make_float4(0.f, 0.f, 0.f, 0.f); v1 = v0;
                }
                int kb = a_half * 8;
                As[kb + 0][a_row] = v0.x; As[kb + 1][a_row] = v0.y;
                As[kb + 2][a_row] = v0.z; As[kb + 3][a_row] = v0.w;
                As[kb + 4][a_row] = v1.x; As[kb + 5][a_row] = v1.y;
                As[kb + 6][a_row] = v1.z; As[kb + 7][a_row] = v1.w;
            }
            // ---- load B tile ----
            {
                int kglob = p * 256 + kt * 16 + b_k;
                const float4* src = (const float4*)(W + (size_t)kglob * 512 + hbase + b_c);
                *(float4*)&Bs[b_k][b_c]     = src[0];
                *(float4*)&Bs[b_k][b_c + 4] = src[1];
            }
            __syncthreads();
            // ---- compute ----
            #pragma unroll
            for (int kk = 0; kk < 16; kk++) {
                float4 a0 = *(const float4*)&As[kk][ty * 8];
                float4 a1 = *(const float4*)&As[kk][ty * 8 + 4];
                ulonglong2 bv0 = *(const ulonglong2*)&Bs[kk][tx * 8];
                ulonglong2 bv1 = *(const ulonglong2*)&Bs[kk][tx * 8 + 4];
                ULL aa[8];
                aa[0] = pack2(a0.x, a0.x); aa[1] = pack2(a0.y, a0.y);
                aa[2] = pack2(a0.z, a0.z); aa[3] = pack2(a0.w, a0.w);
                aa[4] = pack2(a1.x, a1.x); aa[5] = pack2(a1.y, a1.y);
                aa[6] = pack2(a1.z, a1.z); aa[7] = pack2(a1.w, a1.w);
                #pragma unroll
                for (int i = 0; i < 8; i++) {
                    acc[i][0] = fma2(aa[i], bv0.x, acc[i][0]);
                    acc[i][1] = fma2(aa[i], bv0.y, acc[i][1]);
                    acc[i][2] = fma2(aa[i], bv1.x, acc[i][2]);
                    acc[i][3] = fma2(aa[i], bv1.y, acc[i][3]);
                }
            }
        }
    }

    // ---- epilogue: bias + store to g_pre[gate][t][b][h] ----
    #pragma unroll
    for (int i = 0; i < 8; i++) {
        int r = row0 + ty * 8 + i;
        int t = r >> 6, b = r & 63;
        float* dst = g_pre + (((size_t)gate * 16384 + (size_t)t * 64 + b) * 512 + hbase + tx * 8);
        float4 o0, o1;
        unpack2(acc[i][0], o0.x, o0.y); unpack2(acc[i][1], o0.z, o0.w);
        unpack2(acc[i][2], o1.x, o1.y); unpack2(acc[i][3], o1.z, o1.w);
        o0.x += bb[0]; o0.y += bb[1]; o0.z += bb[2]; o0.w += bb[3];
        o1.x += bb[4]; o1.y += bb[5]; o1.z += bb[6]; o1.w += bb[7];
        *(float4*)dst       = o0;
        *((float4*)dst + 1) = o1;
    }
}

// ============================================================================
// Phase 2: persistent LSTM recurrence. 128 CTAs (co-resident on 148 SMs),
// CTA = (16 b) x (16 h); Wh slice cached in smem ONCE (128KB, packed for
// LDS.128 -> 2x f32x2 FMA); software grid barrier per step.
// ============================================================================
__global__ __launch_bounds__(256, 1) void recur_kernel(
    const float* __restrict__ Whf, const float* __restrict__ Whi,
    const float* __restrict__ Whg, const float* __restrict__ Who,
    const float* __restrict__ Wlin, const float* __restrict__ blin,
    float* __restrict__ out)
{
    extern __shared__ float smem[];
    float* ws   = smem;            // 32768 floats: packed Wh slice
    float* hbuf = smem + 32768;    // 8192 floats: [16 b][512 k]

    const int tid = threadIdx.x;
    const int bid = blockIdx.x;
    const int bt = bid & 3;        // b tile (16 rows)
    const int ht = bid >> 2;       // h tile (16 cols), 0..31
    const int bs = tid >> 4, hs = tid & 15;
    const int b = bt * 16 + bs;
    const int h = ht * 16 + hs;

    // ---- pack Wh slice into smem once ----
    // float index e bits: [k2:8][gpair:1][hs:4][gsub:1][kp:1]
    // -> ulonglong2 at (k2*2+gpair)*16+hs holds {(g0 kpair),(g1 kpair)}
    {
        const float* Whs0 = Whf; const float* Whs1 = Whi;
        const float* Whs2 = Whg; const float* Whs3 = Who;
        for (int m = tid; m < 8192; m += 256) {
            int k = m >> 4, hh = m & 15;
            int k2 = k >> 1, kp = k & 1;
            int base = (k2 << 7) | (hh << 2) | kp;
            int col = ht * 16 + hh;
            ws[base | (0 << 6) | (0 << 1)] = Whs0[k * 512 + col];
            ws[base | (0 << 6) | (1 << 1)] = Whs1[k * 512 + col];
            ws[base | (1 << 6) | (0 << 1)] = Whs2[k * 512 + col];
            ws[base | (1 << 6) | (1 << 1)] = Whs3[k * 512 + col];
        }
    }

    const ulonglong2* wsu = (const ulonglong2*)ws;
    float c = 0.f, hval = 0.f;

    for (int t = 0; t < 256; t++) {
        // prefetch x-side pre-activations (DRAM; overlap with smem fill + dots)
        int preoff = (t * 64 + b) * 512 + h;
        float pf = __ldcg(&g_pre[preoff]);
        float pi = __ldcg(&g_pre[preoff +     8388608]);
        float pg = __ldcg(&g_pre[preoff + 2 * 8388608]);
        float po = __ldcg(&g_pre[preoff + 3 * 8388608]);

        // fill hbuf with h_{t-1} for our 16 b rows (L2-only loads: ping-pong buffer)
        if (t == 0) {
            #pragma unroll
            for (int q = 0; q < 8; q++)
                ((float4*)hbuf)[tid + q * 256] = make_float4(0.f, 0.f, 0.f, 0.f);
        } else {
            const float4* src = (const float4*)(g_h[(t - 1) & 1] + bt * 16 * 512);
            #pragma unroll
            for (int q = 0; q < 8; q++) {
                int i4 = tid + q * 256;
                ((float4*)hbuf)[i4] = __ldcg(src + i4);
            }
        }
        __syncthreads();

        ULL a0 = 0ull, a1 = 0ull, a2 = 0ull, a3 = 0ull;
        const ULL* hrow = (const ULL*)(hbuf + bs * 512);
        #pragma unroll 8
        for (int k2 = 0; k2 < 256; k2++) {
            ULL hp = hrow[k2];
            ulonglong2 wa = wsu[(k2 * 2 + 0) * 16 + hs];   // gates 0,1
            ulonglong2 wb = wsu[(k2 * 2 + 1) * 16 + hs];   // gates 2,3
            a0 = fma2(hp, wa.x, a0);
            a1 = fma2(hp, wa.y, a1);
            a2 = fma2(hp, wb.x, a2);
            a3 = fma2(hp, wb.y, a3);
        }
        float lo, hi;
        unpack2(a0, lo, hi); pf += lo + hi;
        unpack2(a1, lo, hi); pi += lo + hi;
        unpack2(a2, lo, hi); pg += lo + hi;
        unpack2(a3, lo, hi); po += lo + hi;

        float f  = 1.f / (1.f + __expf(-pf));
        float ig = 1.f / (1.f + __expf(-pi));
        float gg = tanhf(pg);
        float oo = 1.f / (1.f + __expf(-po));
        c = f * c + ig * gg;
        hval = oo * tanhf(c);

        g_h[t & 1][b * 512 + h] = hval;

        // ---- grid barrier (all 128 CTAs co-resident) ----
        __threadfence();
        __syncthreads();
        if (tid == 0) {
            atomicAdd(&g_bar, 1u);
            unsigned target = (unsigned)(128 * (t + 1));
            while (*((volatile unsigned*)&g_bar) < target) { }
        }
        __syncthreads();
    }

    // ---- outputs: [out(320) | h_t(64x512) | c_t(64x512)] ----
    out[320 + b * 512 + h]         = hval;
    out[320 + 32768 + b * 512 + h] = c;
    if (bid == 0) {
        for (int idx = tid; idx < 320; idx += 256) {
            int bb2 = idx / 5, o = idx % 5;
            float s = blin[o];
            const float* hT = g_h[1] + bb2 * 512;   // 255 & 1 == 1
            for (int k = 0; k < 512; k++)
                s += __ldcg(&hT[k]) * Wlin[k * 5 + o];
            out[idx] = s;
        }
    }
}

__global__ void reset_kernel() { g_bar = 0u; }

extern "C" void kernel_launch(void* const* d_in, const int* in_sizes, int n_in,
                              void* d_out, int out_size)
{
    (void)in_sizes; (void)n_in; (void)out_size;
    const int*   x    = (const int*)d_in[0];
    const float* emb  = (const float*)d_in[1];
    const float* Wfx  = (const float*)d_in[2];
    const float* Wfh  = (const float*)d_in[3];
    const float* bf   = (const float*)d_in[4];
    const float* Wix  = (const float*)d_in[5];
    const float* Wih  = (const float*)d_in[6];
    const float* bi   = (const float*)d_in[7];
    const float* Wgx  = (const float*)d_in[8];
    const float* Wgh  = (const float*)d_in[9];
    const float* bg   = (const float*)d_in[10];
    const float* Wox  = (const float*)d_in[11];
    const float* Woh  = (const float*)d_in[12];
    const float* bo   = (const float*)d_in[13];
    const float* Wlin = (const float*)d_in[14];
    const float* blin = (const float*)d_in[15];
    float* out = (float*)d_out;

    const int SMEM_BYTES = (32768 + 8192) * 4;   // 160KB
    cudaFuncSetAttribute(recur_kernel, cudaFuncAttributeMaxDynamicSharedMemorySize, SMEM_BYTES);

    reset_kernel<<<1, 1>>>();
    dim3 grid(16, 128);
    gemm_x_kernel<<<grid, 256>>>(x, emb, Wfx, Wix, Wgx, Wox, bf, bi, bg, bo);
    recur_kernel<<<128, 256, SMEM_BYTES>>>(Wfh, Wih, Wgh, Woh, Wlin, blin, out);
}

// round 6
// speedup vs baseline: 1.8227x; 1.8227x over previous
#include <cuda_runtime.h>
#include <cuda_bf16.h>
#include <cstdint>

#define ULL unsigned long long

// ---------------- device globals (no cudaMalloc allowed) ----------------
__device__ __align__(1024) float g_pre[4u * 256u * 64u * 512u]; // [gate][t][b][h] 134MB
__device__ __align__(1024) float g_h[2][64 * 512];              // h double buffer
__device__ unsigned g_bar;                                      // grid barrier
__device__ __align__(1024) __nv_bfloat16 g_emb_hi[50000 * 256]; // split-bf16 embedding
__device__ __align__(1024) __nv_bfloat16 g_emb_lo[50000 * 256];
__device__ __align__(1024) __nv_bfloat16 g_WT_hi[2048ull * 4096]; // W transposed [col][k]
__device__ __align__(1024) __nv_bfloat16 g_WT_lo[2048ull * 4096];

// ---------------- helpers ----------------
__device__ __forceinline__ void unpack2(ULL v, float& lo, float& hi) {
    asm("mov.b64 {%0,%1}, %2;" : "=f"(lo), "=f"(hi) : "l"(v));
}
__device__ __forceinline__ ULL fma2(ULL a, ULL b, ULL c) {
    ULL d; asm("fma.rn.f32x2 %0, %1, %2, %3;" : "=l"(d) : "l"(a), "l"(b), "l"(c)); return d;
}
__device__ __forceinline__ uint32_t smem_u32(const void* p) {
    uint32_t a;
    asm("{ .reg .u64 t; cvta.to.shared.u64 t, %1; cvt.u32.u64 %0, t; }" : "=r"(a) : "l"(p));
    return a;
}
__device__ __forceinline__ uint32_t sw128(uint32_t o) { return o ^ ((o >> 3) & 0x70); }

__device__ __forceinline__ void cp_async16(uint32_t dst, const void* src) {
    asm volatile("cp.async.cg.shared.global [%0], [%1], 16;" :: "r"(dst), "l"(src) : "memory");
}
#define CP_COMMIT() asm volatile("cp.async.commit_group;" ::: "memory")
#define CP_WAIT(n)  asm volatile("cp.async.wait_group %0;" :: "n"(n) : "memory")

#define LDSM_X4(r0, r1, r2, r3, addr) \
    asm volatile("ldmatrix.sync.aligned.m8n8.x4.shared.b16 {%0,%1,%2,%3}, [%4];" \
                 : "=r"(r0), "=r"(r1), "=r"(r2), "=r"(r3) : "r"(addr))

__device__ __forceinline__ void mma_bf16(float* d, const uint32_t* a, const uint32_t* b) {
    asm volatile(
        "mma.sync.aligned.m16n8k16.row.col.f32.bf16.bf16.f32 "
        "{%0,%1,%2,%3}, {%4,%5,%6,%7}, {%8,%9}, {%0,%1,%2,%3};"
        : "+f"(d[0]), "+f"(d[1]), "+f"(d[2]), "+f"(d[3])
        : "r"(a[0]), "r"(a[1]), "r"(a[2]), "r"(a[3]), "r"(b[0]), "r"(b[1]));
}

// ============================================================================
// convert kernels
// ============================================================================
__global__ void conv_emb_kernel(const float* __restrict__ emb) {
    size_t i = (size_t)blockIdx.x * 256 + threadIdx.x;   // per float4
    if (i >= 50000u * 64u) return;
    size_t v = i >> 6;
    float4 e = ((const float4*)emb)[i];
    if (v == 0) { e.x = 0.f; e.y = 0.f; e.z = 0.f; e.w = 0.f; }   // padding_idx=0
    __nv_bfloat16 h0 = __float2bfloat16_rn(e.x), h1 = __float2bfloat16_rn(e.y);
    __nv_bfloat16 h2 = __float2bfloat16_rn(e.z), h3 = __float2bfloat16_rn(e.w);
    __nv_bfloat16 l0 = __float2bfloat16_rn(e.x - __bfloat162float(h0));
    __nv_bfloat16 l1 = __float2bfloat16_rn(e.y - __bfloat162float(h1));
    __nv_bfloat16 l2 = __float2bfloat16_rn(e.z - __bfloat162float(h2));
    __nv_bfloat16 l3 = __float2bfloat16_rn(e.w - __bfloat162float(h3));
    __nv_bfloat162* dh = (__nv_bfloat162*)g_emb_hi;
    __nv_bfloat162* dl = (__nv_bfloat162*)g_emb_lo;
    dh[i * 2]     = __nv_bfloat162(h0, h1);
    dh[i * 2 + 1] = __nv_bfloat162(h2, h3);
    dl[i * 2]     = __nv_bfloat162(l0, l1);
    dl[i * 2 + 1] = __nv_bfloat162(l2, l3);
}

// transpose+convert two gate weight matrices: W[k=4096][h=512] -> WT[c=g*512+h][k]
__global__ void conv_wt_kernel(const float* __restrict__ Wa, const float* __restrict__ Wb,
                               int gbase) {
    const float* W = (blockIdx.z == 0) ? Wa : Wb;
    int cb = (gbase + blockIdx.z) * 512;
    __shared__ __nv_bfloat16 th[32][33], tl[32][33];
    int k0 = blockIdx.x * 32, h0 = blockIdx.y * 32;
    int tx = threadIdx.x & 31, ty = threadIdx.x >> 5;
    #pragma unroll
    for (int q = 0; q < 4; q++) {
        int r = ty + q * 8;
        float f = W[(size_t)(k0 + r) * 512 + h0 + tx];
        __nv_bfloat16 hi = __float2bfloat16_rn(f);
        th[r][tx] = hi;
        tl[r][tx] = __float2bfloat16_rn(f - __bfloat162float(hi));
    }
    __syncthreads();
    #pragma unroll
    for (int q = 0; q < 4; q++) {
        int rr = ty + q * 8;
        g_WT_hi[(size_t)(cb + h0 + rr) * 4096 + k0 + tx] = th[tx][rr];
        g_WT_lo[(size_t)(cb + h0 + rr) * 4096 + k0 + tx] = tl[tx][rr];
    }
}

// ============================================================================
// Phase 1: mma.sync split-bf16 gathered GEMM
//   C[16384, 2048] = A x Wcat; CTA tile M=128, N=128, BK=64, 3-stage cp.async
//   3 terms: Ahi*Bhi + Ahi*Blo + Alo*Bhi (fp32 accum)  -> g_pre + bias
// ============================================================================
#define SIDX_OFF  0u
#define SA_HI(s)  (8192u + (uint32_t)(s) * 65536u)
#define SA_LO(s)  (SA_HI(s) + 16384u)
#define SB_HI(s)  (SA_HI(s) + 32768u)
#define SB_LO(s)  (SA_HI(s) + 49152u)
#define GEMM_SMEM (8192u + 3u * 65536u)   // 204800 B

__device__ __forceinline__ void load_stage(uint32_t smem_base, const int* sidx_s,
                                           int s, int buf, int n0, int tid)
{
    const int k0 = s * 64;
    const int p = k0 >> 8;
    const int i0 = k0 & 255;
    const int r = tid >> 1, half = tid & 1;
    // ---- A: gathered rows from split embedding ----
    int idx = sidx_s[p * 128 + r];
    const char* srcAh = (const char*)(g_emb_hi + (size_t)idx * 256 + i0 + half * 32);
    const char* srcAl = (const char*)(g_emb_lo + (size_t)idx * 256 + i0 + half * 32);
    uint32_t dA = (uint32_t)(r * 128 + half * 64);
    #pragma unroll
    for (int j = 0; j < 4; j++) {
        uint32_t so = sw128(dA + j * 16);
        cp_async16(smem_base + SA_HI(buf) + so, srcAh + j * 16);
        cp_async16(smem_base + SA_LO(buf) + so, srcAl + j * 16);
    }
    // ---- B: WT rows (n-major, k contiguous) ----
    const char* srcBh = (const char*)(g_WT_hi + (size_t)(n0 + r) * 4096 + k0 + half * 32);
    const char* srcBl = (const char*)(g_WT_lo + (size_t)(n0 + r) * 4096 + k0 + half * 32);
    #pragma unroll
    for (int j = 0; j < 4; j++) {
        uint32_t so = sw128(dA + j * 16);
        cp_async16(smem_base + SB_HI(buf) + so, srcBh + j * 16);
        cp_async16(smem_base + SB_LO(buf) + so, srcBl + j * 16);
    }
}

__global__ __launch_bounds__(256, 1) void gemm_x_kernel(
    const int* __restrict__ x,
    const float* __restrict__ b0, const float* __restrict__ b1,
    const float* __restrict__ b2, const float* __restrict__ b3)
{
    extern __shared__ char smem[];
    const uint32_t smem_base = smem_u32(smem);
    int* sidx_s = (int*)smem;                  // [16][128]

    const int tid = threadIdx.x;
    const int wid = tid >> 5, lane = tid & 31;
    const int bx = blockIdx.x;                 // n tile (0..15)
    const int by = blockIdx.y;                 // m tile (0..127)
    const int n0 = bx * 128;
    const int row0 = by * 128;
    const int m_off = (wid >> 1) * 32;
    const int n_off = (wid & 1) * 64;

    // ---- preload gather indices for all 16 POS tags ----
    for (int i = tid; i < 2048; i += 256) {
        int p = i >> 7, r = i & 127;
        int rg = row0 + r;
        int t = rg >> 6, b = rg & 63;
        sidx_s[i] = __ldg(x + (b * 16 + p) * 256 + t);
    }
    __syncthreads();

    load_stage(smem_base, sidx_s, 0, 0, n0, tid); CP_COMMIT();
    load_stage(smem_base, sidx_s, 1, 1, n0, tid); CP_COMMIT();

    float acc[2][8][4];
    #pragma unroll
    for (int mt = 0; mt < 2; mt++)
        #pragma unroll
        for (int nf = 0; nf < 8; nf++)
            #pragma unroll
            for (int j = 0; j < 4; j++) acc[mt][nf][j] = 0.f;

    // lane address components
    const int arow = lane & 15, achunk = lane >> 4;        // A ldmatrix
    const int bj = lane >> 3, br = lane & 7;               // B ldmatrix
    const int bnadd = ((bj >> 1) * 8 + br), bkc = (bj & 1);

    for (int s = 0; s < 64; s++) {
        const int buf = s % 3;
        CP_WAIT(1);           // stage s resident (s+1 may still be in flight)
        __syncthreads();
        if (s + 2 < 64) load_stage(smem_base, sidx_s, s + 2, (s + 2) % 3, n0, tid);
        CP_COMMIT();

        #pragma unroll
        for (int k16 = 0; k16 < 4; k16++) {
            const int kb = k16 * 32;
            uint32_t a_hi[2][4], a_lo[2][4], b_hi[4][4], b_lo[4][4];
            #pragma unroll
            for (int mt = 0; mt < 2; mt++) {
                uint32_t off = sw128((uint32_t)((m_off + mt * 16 + arow) * 128 + kb + achunk * 16));
                LDSM_X4(a_hi[mt][0], a_hi[mt][1], a_hi[mt][2], a_hi[mt][3],
                        smem_base + SA_HI(buf) + off);
                LDSM_X4(a_lo[mt][0], a_lo[mt][1], a_lo[mt][2], a_lo[mt][3],
                        smem_base + SA_LO(buf) + off);
            }
            #pragma unroll
            for (int ng = 0; ng < 4; ng++) {
                uint32_t off = sw128((uint32_t)((n_off + ng * 16 + bnadd) * 128 + kb + bkc * 16));
                LDSM_X4(b_hi[ng][0], b_hi[ng][1], b_hi[ng][2], b_hi[ng][3],
                        smem_base + SB_HI(buf) + off);
                LDSM_X4(b_lo[ng][0], b_lo[ng][1], b_lo[ng][2], b_lo[ng][3],
                        smem_base + SB_LO(buf) + off);
            }
            #pragma unroll
            for (int mt = 0; mt < 2; mt++) {
                #pragma unroll
                for (int nf = 0; nf < 8; nf++) {
                    const int ng = nf >> 1, sub = (nf & 1) * 2;
                    mma_bf16(acc[mt][nf], a_hi[mt], &b_hi[ng][sub]);
                    mma_bf16(acc[mt][nf], a_hi[mt], &b_lo[ng][sub]);
                    mma_bf16(acc[mt][nf], a_lo[mt], &b_hi[ng][sub]);
                }
            }
        }
    }

    // ---- epilogue: bias + store to g_pre[gate][t][b][h] ----
    const int gate = bx >> 2;
    const int hbase = (bx & 3) * 128;
    const float* bias = (gate == 0) ? b0 : (gate == 1) ? b1 : (gate == 2) ? b2 : b3;
    #pragma unroll
    for (int mt = 0; mt < 2; mt++) {
        #pragma unroll
        for (int nf = 0; nf < 8; nf++) {
            int h = hbase + n_off + nf * 8 + (lane & 3) * 2;
            float bv0 = __ldg(bias + h), bv1 = __ldg(bias + h + 1);
            int rg0 = row0 + m_off + mt * 16 + (lane >> 2);
            {
                int t = rg0 >> 6, b = rg0 & 63;
                float2 v = make_float2(acc[mt][nf][0] + bv0, acc[mt][nf][1] + bv1);
                *(float2*)(g_pre + ((size_t)gate * 16384 + (size_t)t * 64 + b) * 512 + h) = v;
            }
            {
                int rg1 = rg0 + 8;
                int t = rg1 >> 6, b = rg1 & 63;
                float2 v = make_float2(acc[mt][nf][2] + bv0, acc[mt][nf][3] + bv1);
                *(float2*)(g_pre + ((size_t)gate * 16384 + (size_t)t * 64 + b) * 512 + h) = v;
            }
        }
    }
}

// ============================================================================
// Phase 2: persistent LSTM recurrence (128 co-resident CTAs, grid barrier)
// CTA = 16b x 16h; warp = 16 bs x 2 hs (W broadcast across bs); hbuf padded
// to 516 floats/row so h pair-loads are phase-conflict-free.
// ============================================================================
#define HS_STRIDE 516
#define RECUR_SMEM ((32768 + 16 * HS_STRIDE) * 4)

__global__ __launch_bounds__(256, 1) void recur_kernel(
    const float* __restrict__ Whf, const float* __restrict__ Whi,
    const float* __restrict__ Whg, const float* __restrict__ Who,
    const float* __restrict__ Wlin, const float* __restrict__ blin,
    float* __restrict__ out)
{
    extern __shared__ float fsmem[];
    float* ws   = fsmem;               // 32768 floats: packed Wh slice
    float* hbuf = fsmem + 32768;       // 16 * 516 floats

    const int tid = threadIdx.x;
    const int bid = blockIdx.x;
    const int bt = bid & 3, ht = bid >> 2;
    const int bs = tid & 15, hs = tid >> 4;
    const int b = bt * 16 + bs;
    const int h = ht * 16 + hs;

    // pack Wh slice: ulonglong2 at (k2*2+gp)*16+hh = {gateA kpair, gateB kpair}
    for (int m = tid; m < 8192; m += 256) {
        int k = m >> 4, hh = m & 15;
        int k2 = k >> 1, kp = k & 1;
        int base = (k2 << 7) | (hh << 2) | kp;
        int col = ht * 16 + hh;
        ws[base | (0 << 6) | (0 << 1)] = Whf[k * 512 + col];
        ws[base | (0 << 6) | (1 << 1)] = Whi[k * 512 + col];
        ws[base | (1 << 6) | (0 << 1)] = Whg[k * 512 + col];
        ws[base | (1 << 6) | (1 << 1)] = Who[k * 512 + col];
    }

    const ulonglong2* wsu = (const ulonglong2*)ws;
    float c = 0.f, hval = 0.f;

    for (int t = 0; t < 256; t++) {
        int preoff = (t * 64 + b) * 512 + h;
        float pf = __ldcg(&g_pre[preoff]);
        float pi = __ldcg(&g_pre[preoff +     8388608]);
        float pg = __ldcg(&g_pre[preoff + 2 * 8388608]);
        float po = __ldcg(&g_pre[preoff + 3 * 8388608]);

        if (t == 0) {
            #pragma unroll
            for (int q = 0; q < 8; q++) {
                int i4 = tid + q * 256;
                int bi = i4 >> 7, rem = i4 & 127;
                *(float4*)(hbuf + bi * HS_STRIDE + rem * 4) = make_float4(0.f, 0.f, 0.f, 0.f);
            }
        } else {
            const float4* src = (const float4*)(g_h[(t - 1) & 1] + bt * 16 * 512);
            #pragma unroll
            for (int q = 0; q < 8; q++) {
                int i4 = tid + q * 256;
                int bi = i4 >> 7, rem = i4 & 127;
                *(float4*)(hbuf + bi * HS_STRIDE + rem * 4) = __ldcg(src + i4);
            }
        }
        __syncthreads();

        ULL a0 = 0ull, a1 = 0ull, a2 = 0ull, a3 = 0ull;
        const ulonglong2* hrow = (const ulonglong2*)(hbuf + bs * HS_STRIDE);
        #pragma unroll 4
        for (int k4 = 0; k4 < 128; k4++) {
            ulonglong2 hp = hrow[k4];
            int k2a = k4 * 2;
            ulonglong2 wa0 = wsu[(k2a * 2 + 0) * 16 + hs];
            ulonglong2 wb0 = wsu[(k2a * 2 + 1) * 16 + hs];
            ulonglong2 wa1 = wsu[(k2a * 2 + 2) * 16 + hs];
            ulonglong2 wb1 = wsu[(k2a * 2 + 3) * 16 + hs];
            a0 = fma2(hp.x, wa0.x, a0); a1 = fma2(hp.x, wa0.y, a1);
            a2 = fma2(hp.x, wb0.x, a2); a3 = fma2(hp.x, wb0.y, a3);
            a0 = fma2(hp.y, wa1.x, a0); a1 = fma2(hp.y, wa1.y, a1);
            a2 = fma2(hp.y, wb1.x, a2); a3 = fma2(hp.y, wb1.y, a3);
        }
        float lo, hi;
        unpack2(a0, lo, hi); pf += lo + hi;
        unpack2(a1, lo, hi); pi += lo + hi;
        unpack2(a2, lo, hi); pg += lo + hi;
        unpack2(a3, lo, hi); po += lo + hi;

        float f  = 1.f / (1.f + __expf(-pf));
        float ig = 1.f / (1.f + __expf(-pi));
        float gg = tanhf(pg);
        float oo = 1.f / (1.f + __expf(-po));
        c = f * c + ig * gg;
        hval = oo * tanhf(c);

        g_h[t & 1][b * 512 + h] = hval;

        // grid barrier (all 128 CTAs co-resident)
        __threadfence();
        __syncthreads();
        if (tid == 0) {
            atomicAdd(&g_bar, 1u);
            unsigned target = (unsigned)(128 * (t + 1));
            while (*((volatile unsigned*)&g_bar) < target) { }
        }
        __syncthreads();
    }

    // outputs: [out(320) | h_t(64x512) | c_t(64x512)]
    out[320 + b * 512 + h]         = hval;
    out[320 + 32768 + b * 512 + h] = c;
    if (bid == 0) {
        for (int idx = tid; idx < 320; idx += 256) {
            int bb2 = idx / 5, o = idx % 5;
            float s = blin[o];
            const float* hT = g_h[1] + bb2 * 512;   // t=255 -> buffer 1
            for (int k = 0; k < 512; k++)
                s += __ldcg(&hT[k]) * Wlin[k * 5 + o];
            out[idx] = s;
        }
    }
}

__global__ void reset_kernel() { g_bar = 0u; }

extern "C" void kernel_launch(void* const* d_in, const int* in_sizes, int n_in,
                              void* d_out, int out_size)
{
    (void)in_sizes; (void)n_in; (void)out_size;
    const int*   x    = (const int*)d_in[0];
    const float* emb  = (const float*)d_in[1];
    const float* Wfx  = (const float*)d_in[2];
    const float* Wfh  = (const float*)d_in[3];
    const float* bf   = (const float*)d_in[4];
    const float* Wix  = (const float*)d_in[5];
    const float* Wih  = (const float*)d_in[6];
    const float* bi   = (const float*)d_in[7];
    const float* Wgx  = (const float*)d_in[8];
    const float* Wgh  = (const float*)d_in[9];
    const float* bg   = (const float*)d_in[10];
    const float* Wox  = (const float*)d_in[11];
    const float* Woh  = (const float*)d_in[12];
    const float* bo   = (const float*)d_in[13];
    const float* Wlin = (const float*)d_in[14];
    const float* blin = (const float*)d_in[15];
    float* out = (float*)d_out;

    cudaFuncSetAttribute(gemm_x_kernel, cudaFuncAttributeMaxDynamicSharedMemorySize, GEMM_SMEM);
    cudaFuncSetAttribute(recur_kernel, cudaFuncAttributeMaxDynamicSharedMemorySize, RECUR_SMEM);

    // 7 launches/replay -> ncu (-s 5 -c 1) lands on gemm_x_kernel (index 5)
    reset_kernel<<<1, 1>>>();
    conv_emb_kernel<<<(50000 * 64 + 255) / 256, 256>>>(emb);
    conv_wt_kernel<<<dim3(128, 16, 2), 256>>>(Wfx, Wix, 0);
    conv_wt_kernel<<<dim3(128, 16, 2), 256>>>(Wgx, Wox, 2);
    reset_kernel<<<1, 1>>>();
    gemm_x_kernel<<<dim3(16, 128), 256, GEMM_SMEM>>>(x, bf, bi, bg, bo);
    recur_kernel<<<128, 256, RECUR_SMEM>>>(Wfh, Wih, Wgh, Woh, Wlin, blin, out);
}